// round 14
// baseline (speedup 1.0000x reference)
#include <cuda_runtime.h>
#include <cuda_bf16.h>
#include <cstdint>
#include <cstddef>

// Problem dims
constexpr int BB = 16, CC = 24, SS = 128, EE = 256, HH = 8, PP = 32;
constexpr int NTOT  = BB * CC * SS * EE;     // 12,582,912
constexpr int NROWS = BB * CC * SS;          // 49,152
constexpr int WELEMS = CC * EE * EE;         // 1,572,864 per weight
constexpr int NW = 10;
constexpr float LN_EPS = 1e-6f;
constexpr float INV_SQRT_P = 0.17677669529663687f;

// ---------------------------------------------------------------------------
// Device scratch
// ---------------------------------------------------------------------------
__device__ float g_qs[NTOT], g_ks[NTOT], g_vs[NTOT];
__device__ float g_qt[NTOT], g_kt[NTOT], g_vt[NTOT];
__device__ float g_spat[NTOT], g_temp[NTOT], g_attn[NTOT], g_ffo[NTOT];
__device__ __align__(16) __nv_bfloat16 g_ah[NTOT], g_al[NTOT];   // spatial-out / attn pair
__device__ __align__(16) __nv_bfloat16 g_hh[NTOT], g_hl[NTOT];   // temporal-out / ff hidden pair
__device__ __align__(16) __nv_bfloat16 g_wh[NW * WELEMS], g_wl[NW * WELEMS];

// ---------------------------------------------------------------------------
// PTX helpers (baseline ISA only)
// ---------------------------------------------------------------------------
__device__ __forceinline__ uint32_t smem_u32(const void* p) {
    uint32_t a;
    asm("{ .reg .u64 t; cvta.to.shared.u64 t, %1; cvt.u32.u64 %0, t; }"
        : "=r"(a) : "l"(p));
    return a;
}
__device__ __forceinline__ void cp_async16(uint32_t smem, const void* gmem) {
    asm volatile("cp.async.cg.shared.global [%0], [%1], 16;"
                 :: "r"(smem), "l"(gmem));
}
__device__ __forceinline__ void cp_commit() {
    asm volatile("cp.async.commit_group;");
}
template <int N>
__device__ __forceinline__ void cp_wait() {
    asm volatile("cp.async.wait_group %0;" :: "n"(N) : "memory");
}
__device__ __forceinline__ void ldsm_x4(uint32_t& r0, uint32_t& r1,
                                        uint32_t& r2, uint32_t& r3, uint32_t addr) {
    asm volatile("ldmatrix.sync.aligned.m8n8.x4.shared.b16 {%0,%1,%2,%3}, [%4];"
                 : "=r"(r0), "=r"(r1), "=r"(r2), "=r"(r3) : "r"(addr));
}
__device__ __forceinline__ void mma_bf16(float* d, const uint32_t* a,
                                         uint32_t b0, uint32_t b1) {
    asm volatile(
        "mma.sync.aligned.m16n8k16.row.col.f32.bf16.bf16.f32 "
        "{%0,%1,%2,%3}, {%4,%5,%6,%7}, {%8,%9}, {%0,%1,%2,%3};"
        : "+f"(d[0]), "+f"(d[1]), "+f"(d[2]), "+f"(d[3])
        : "r"(a[0]), "r"(a[1]), "r"(a[2]), "r"(a[3]), "r"(b0), "r"(b1));
}
// packed f32x2
__device__ __forceinline__ unsigned long long pack2(float v) {
    unsigned long long r;
    asm("mov.b64 %0, {%1, %1};" : "=l"(r) : "f"(v));
    return r;
}
__device__ __forceinline__ void fma2(unsigned long long& d,
                                     unsigned long long a, unsigned long long b) {
    asm("fma.rn.f32x2 %0, %1, %2, %0;" : "+l"(d) : "l"(a), "l"(b));
}
__device__ __forceinline__ float2 unpack2(unsigned long long v) {
    float2 f;
    asm("mov.b64 {%0, %1}, %2;" : "=f"(f.x), "=f"(f.y) : "l"(v));
    return f;
}

// ---------------------------------------------------------------------------
// bf16 hi/lo split helpers
// ---------------------------------------------------------------------------
__device__ __forceinline__ void split_bf16(float x, __nv_bfloat16& h, __nv_bfloat16& l) {
    h = __float2bfloat16_rn(x);
    l = __float2bfloat16_rn(x - __bfloat162float(h));
}
__device__ __forceinline__ uint32_t pack_bf16x2(float a, float b) {
    __nv_bfloat162 t = __halves2bfloat162(__float2bfloat16_rn(a), __float2bfloat16_rn(b));
    return *(uint32_t*)&t;
}
__device__ __forceinline__ float bf16_lo_res(float x) {
    return x - __bfloat162float(__float2bfloat16_rn(x));
}

// ---------------------------------------------------------------------------
// Weight conversion, coalesced: 32x32 (e,f) tiles via smem transpose.
// ---------------------------------------------------------------------------
struct WPtrs { const float* p[NW]; };

__global__ __launch_bounds__(256) void convert_weights_t(
    WPtrs wp, __nv_bfloat16* __restrict__ wh, __nv_bfloat16* __restrict__ wl)
{
    __shared__ float tile[32][33];
    const int w = blockIdx.z, c = blockIdx.y;
    const int eb = blockIdx.x & 7, fb = blockIdx.x >> 3;
    const int mode = (w == 3 || w >= 7) ? 0 : (w == 0 ? 1 : (w <= 2 ? 2 : 3));
    const int t = threadIdx.x;
    const int col = t & 31, r0 = t >> 5;
    const float* W = wp.p[w];

#pragma unroll
    for (int i = 0; i < 4; ++i) {
        const int row = r0 + i * 8;
        float v;
        if (mode == 0) {
            const int e = eb * 32 + row, f = fb * 32 + col;
            v = W[((size_t)c * EE + e) * EE + f];
        } else if (mode == 1) {
            const int f = fb * 32 + row, e = eb * 32 + col;
            const int h = fb, p = f & 31;
            v = W[(((size_t)h * CC + c) * PP + p) * EE + e];
        } else if (mode == 2) {
            const int e = eb * 32 + row, p = col, h = fb;
            v = W[((size_t)h * EE + e) * PP + p];
        } else {
            const int e = eb * 32 + row, p = col, h = fb;
            v = W[(((size_t)h * CC + c) * EE + e) * PP + p];
        }
        tile[row][col] = v;
    }
    __syncthreads();

#pragma unroll
    for (int i = 0; i < 4; ++i) {
        const int fr = r0 + i * 8;
        const int f = fb * 32 + fr;
        const int e = eb * 32 + col;
        const float v = (mode == 1) ? tile[fr][col] : tile[col][fr];
        __nv_bfloat16 hi, lo;
        split_bf16(v, hi, lo);
        const size_t o = (size_t)w * WELEMS + ((size_t)c << 16) + (size_t)f * EE + e;
        wh[o] = hi;
        wl[o] = lo;
    }
}

// ---------------------------------------------------------------------------
// Fused QKVx6 GEMM v3: A resident (in-kernel split), block M=128 x N=256,
// 512 threads / 16 warps (4 warps per SMSP) with 32x64 warp tiles.
// 48 B-stages double-buffered.
// ---------------------------------------------------------------------------
constexpr int AP = 528;
constexpr int QA_HI = 0;
constexpr int QA_LO = 128 * AP;
constexpr int QB0   = 2 * 128 * AP;            // 135168
constexpr int GP = 80;
constexpr int QB_LO  = 256 * GP;               // 20480 (within stage)
constexpr int QB_STG = 2 * 256 * GP;           // 40960
constexpr int QKV_SMEM = QB0 + 2 * QB_STG;     // 217088

struct Out6 { float* y[6]; };

__global__ __launch_bounds__(512) void gemm_qkv6(
    const float* __restrict__ x,
    const __nv_bfloat16* __restrict__ whB, const __nv_bfloat16* __restrict__ wlB,
    Out6 outs)
{
    extern __shared__ __align__(16) char dsm[];
    const uint32_t sbase = smem_u32(dsm);
    const int tid = threadIdx.x;
    const int wid = tid >> 5, lane = tid & 31;
    const int b = blockIdx.x, c = blockIdx.z;

    const size_t abase = ((size_t)b * CC + c) * SS * EE;

    // stage s: weight w = s>>3, K-chunk kc = s&7 (32 wide); B covers all 256 f.
    auto issueB = [&](int stage) {
        const int w = stage >> 3, kb = (stage & 7) * 32;
        const int wg = w + (w >= 3);           // 0,1,2,4,5,6
        const __nv_bfloat16* Wh = whB + (size_t)wg * WELEMS + ((size_t)c << 16);
        const __nv_bfloat16* Wl = wlB + (size_t)wg * WELEMS + ((size_t)c << 16);
        const uint32_t sb = sbase + QB0 + (stage & 1) * QB_STG;
#pragma unroll
        for (int j = 0; j < 2; ++j) {
            const int t2 = tid + j * 512;      // 0..1023 = 256 rows x 4 chunks
            const int row = t2 >> 2, ch = t2 & 3;
            const size_t goff = (size_t)row * EE + kb + ch * 8;
            const uint32_t so = row * GP + ch * 16;
            cp_async16(sb + so, Wh + goff);
            cp_async16(sb + QB_LO + so, Wl + goff);
        }
    };
    issueB(0); cp_commit();
    issueB(1); cp_commit();

    // ---- load A from fp32 x, split to bf16 hi/lo in smem ----
#pragma unroll
    for (int i = 0; i < 8; ++i) {
        const int t2 = tid + i * 512;          // 0..4095
        const int row = t2 >> 5, ch = t2 & 31;
        const float* src = x + abase + (size_t)row * EE + ch * 8;
        float4 v0 = *(const float4*)src;
        float4 v1 = *(const float4*)(src + 4);
        float vv[8] = {v0.x, v0.y, v0.z, v0.w, v1.x, v1.y, v1.z, v1.w};
        __nv_bfloat16 h[8], l[8];
#pragma unroll
        for (int j = 0; j < 8; ++j) split_bf16(vv[j], h[j], l[j]);
        uint4 hp, lp;
        ((__nv_bfloat162*)&hp)[0] = __halves2bfloat162(h[0], h[1]);
        ((__nv_bfloat162*)&hp)[1] = __halves2bfloat162(h[2], h[3]);
        ((__nv_bfloat162*)&hp)[2] = __halves2bfloat162(h[4], h[5]);
        ((__nv_bfloat162*)&hp)[3] = __halves2bfloat162(h[6], h[7]);
        ((__nv_bfloat162*)&lp)[0] = __halves2bfloat162(l[0], l[1]);
        ((__nv_bfloat162*)&lp)[1] = __halves2bfloat162(l[2], l[3]);
        ((__nv_bfloat162*)&lp)[2] = __halves2bfloat162(l[4], l[5]);
        ((__nv_bfloat162*)&lp)[3] = __halves2bfloat162(l[6], l[7]);
        const uint32_t so = row * AP + ch * 16;
        *(uint4*)(dsm + QA_HI + so) = hp;
        *(uint4*)(dsm + QA_LO + so) = lp;
    }

    // 16 warps: 4 m-groups (32 rows) x 4 n-groups (64 cols)
    const int wm = wid & 3, wn = wid >> 2;
    const int g = lane >> 3, lr = lane & 7;

    for (int w = 0; w < 6; ++w) {
        float acc[2][8][4];
#pragma unroll
        for (int mi = 0; mi < 2; ++mi)
#pragma unroll
            for (int nj = 0; nj < 8; ++nj)
#pragma unroll
                for (int r = 0; r < 4; ++r) acc[mi][nj][r] = 0.f;

        for (int kc = 0; kc < 8; ++kc) {
            const int stage = w * 8 + kc;
            cp_wait<1>();
            __syncthreads();
            const uint32_t Bst = sbase + QB0 + (stage & 1) * QB_STG;

#pragma unroll
            for (int pass = 0; pass < 3; ++pass) {
                const uint32_t Ab = sbase + (pass == 2 ? QA_LO : QA_HI);
                const uint32_t Bb = Bst + (pass == 1 ? QB_LO : 0);
#pragma unroll
                for (int k16 = 0; k16 < 2; ++k16) {
                    uint32_t afr[2][4];
#pragma unroll
                    for (int mi = 0; mi < 2; ++mi) {
                        const int row = wm * 32 + mi * 16 + ((g & 1) << 3) + lr;
                        const uint32_t addr =
                            Ab + row * AP + (kc * 4 + k16 * 2 + (g >> 1)) * 16;
                        ldsm_x4(afr[mi][0], afr[mi][1], afr[mi][2], afr[mi][3], addr);
                    }
                    uint32_t bfr[4][4];
#pragma unroll
                    for (int ni = 0; ni < 4; ++ni) {
                        const int row = wn * 64 + ni * 16 + ((g >> 1) << 3) + lr;
                        const uint32_t addr = Bb + row * GP + (k16 * 2 + (g & 1)) * 16;
                        ldsm_x4(bfr[ni][0], bfr[ni][1], bfr[ni][2], bfr[ni][3], addr);
                    }
#pragma unroll
                    for (int mi = 0; mi < 2; ++mi)
#pragma unroll
                        for (int nj = 0; nj < 8; ++nj)
                            mma_bf16(acc[mi][nj], afr[mi],
                                     bfr[nj >> 1][(nj & 1) * 2],
                                     bfr[nj >> 1][(nj & 1) * 2 + 1]);
                }
            }
            __syncthreads();
            if (stage + 2 < 48) issueB(stage + 2);
            cp_commit();
        }

        float* Yf = outs.y[w];
#pragma unroll
        for (int mi = 0; mi < 2; ++mi)
#pragma unroll
            for (int rr = 0; rr < 2; ++rr) {
                const int m = wm * 32 + mi * 16 + (lane >> 2) + rr * 8;
                const size_t yrow = abase + (size_t)m * EE;
#pragma unroll
                for (int nj = 0; nj < 8; ++nj) {
                    const int colo = wn * 64 + nj * 8 + (lane & 3) * 2;
                    *(float2*)(Yf + yrow + colo) =
                        make_float2(acc[mi][nj][rr * 2 + 0], acc[mi][nj][rr * 2 + 1]);
                }
            }
    }
}

// ---------------------------------------------------------------------------
// Generic HMMA GEMM body v2: 256(M)x128(N) block (2 b-slices), 64x64 warp tiles.
// ---------------------------------------------------------------------------
constexpr int T_A_HI = 0;
constexpr int T_A_LO = 256 * GP;              // 20480
constexpr int T_B_HI = 2 * 256 * GP;          // 40960
constexpr int T_B_LO = T_B_HI + 128 * GP;     // 51200
constexpr int STAGE  = T_B_LO + 128 * GP;     // 61440
constexpr int GEMM_SMEM = 2 * STAGE;          // 122880

template <int EPI>
__device__ __forceinline__ void gemm_body(
    const __nv_bfloat16* __restrict__ Ah, const __nv_bfloat16* __restrict__ Al,
    const __nv_bfloat16* __restrict__ Wh, const __nv_bfloat16* __restrict__ Wl,
    const float* __restrict__ bias,
    float* __restrict__ Yf,
    __nv_bfloat16* __restrict__ Yh, __nv_bfloat16* __restrict__ Yl,
    int b0, int nb, int c, uint32_t sbase)
{
    const int tid = threadIdx.x;
    const int wid = tid >> 5, lane = tid & 31;

    const size_t abase0 = ((size_t)b0 * CC + c) * SS * EE;
    const size_t bstride = (size_t)CC * SS * EE;
    const size_t wbase = (size_t)c * EE * EE + (size_t)nb * 128 * EE;

    auto issue = [&](int stg) {
        const int kb = stg * 32;
        const uint32_t sb = sbase + (stg & 1) * STAGE;
#pragma unroll
        for (int j = 0; j < 4; ++j) {
            const int t2 = tid + j * 256;
            const int row = t2 >> 2, ch = t2 & 3;
            const int bo = row >> 7, s = row & 127;
            const size_t goff = abase0 + (size_t)bo * bstride + (size_t)s * EE + kb + ch * 8;
            const uint32_t so = row * GP + ch * 16;
            cp_async16(sb + T_A_HI + so, Ah + goff);
            cp_async16(sb + T_A_LO + so, Al + goff);
        }
#pragma unroll
        for (int j = 0; j < 2; ++j) {
            const int t2 = tid + j * 256;
            const int row = t2 >> 2, ch = t2 & 3;
            const size_t goff = wbase + (size_t)row * EE + kb + ch * 8;
            const uint32_t so = row * GP + ch * 16;
            cp_async16(sb + T_B_HI + so, Wh + goff);
            cp_async16(sb + T_B_LO + so, Wl + goff);
        }
    };
    issue(0); cp_commit();
    issue(1); cp_commit();

    const int wm = wid & 3, wn = wid >> 2;
    const int g = lane >> 3, lr = lane & 7;

    float acc[4][8][4];
#pragma unroll
    for (int mi = 0; mi < 4; ++mi)
#pragma unroll
        for (int nj = 0; nj < 8; ++nj)
#pragma unroll
            for (int r = 0; r < 4; ++r) acc[mi][nj][r] = 0.f;

    for (int it = 0; it < 8; ++it) {
        cp_wait<1>();
        __syncthreads();
        const uint32_t st = sbase + (it & 1) * STAGE;

#pragma unroll
        for (int pass = 0; pass < 3; ++pass) {
            const uint32_t Ab = st + (pass == 2 ? T_A_LO : T_A_HI);
            const uint32_t Bb = st + (pass == 1 ? T_B_LO : T_B_HI);
#pragma unroll
            for (int k16 = 0; k16 < 2; ++k16) {
                uint32_t afr[4][4];
#pragma unroll
                for (int mi = 0; mi < 4; ++mi) {
                    const int row = wm * 64 + mi * 16 + ((g & 1) << 3) + lr;
                    const uint32_t addr = Ab + row * GP + (k16 * 2 + (g >> 1)) * 16;
                    ldsm_x4(afr[mi][0], afr[mi][1], afr[mi][2], afr[mi][3], addr);
                }
                uint32_t bfr[4][4];
#pragma unroll
                for (int ni = 0; ni < 4; ++ni) {
                    const int row = wn * 64 + ni * 16 + ((g >> 1) << 3) + lr;
                    const uint32_t addr = Bb + row * GP + (k16 * 2 + (g & 1)) * 16;
                    ldsm_x4(bfr[ni][0], bfr[ni][1], bfr[ni][2], bfr[ni][3], addr);
                }
#pragma unroll
                for (int mi = 0; mi < 4; ++mi)
#pragma unroll
                    for (int nj = 0; nj < 8; ++nj)
                        mma_bf16(acc[mi][nj], afr[mi],
                                 bfr[nj >> 1][(nj & 1) * 2],
                                 bfr[nj >> 1][(nj & 1) * 2 + 1]);
            }
        }
        __syncthreads();
        if (it + 2 < 8) issue(it + 2);
        cp_commit();
    }

#pragma unroll
    for (int mi = 0; mi < 4; ++mi) {
#pragma unroll
        for (int rr = 0; rr < 2; ++rr) {
            const int m = wm * 64 + mi * 16 + (lane >> 2) + rr * 8;
            const int bo = m >> 7, s = m & 127;
            const size_t yrow = abase0 + (size_t)bo * bstride + (size_t)s * EE + nb * 128;
#pragma unroll
            for (int nj = 0; nj < 8; ++nj) {
                const int col = wn * 64 + nj * 8 + (lane & 3) * 2;
                float v0 = acc[mi][nj][rr * 2 + 0];
                float v1 = acc[mi][nj][rr * 2 + 1];
                if constexpr (EPI == 0) {
                    *(float2*)(Yf + yrow + col) = make_float2(v0, v1);
                } else {
                    const float* bp = bias + (size_t)c * EE + nb * 128 + col;
                    v0 += bp[0];
                    v1 += bp[1];
                    if constexpr (EPI == 1) {
                        v0 = fmaxf(v0, 0.f);
                        v1 = fmaxf(v1, 0.f);
                        __nv_bfloat16 h0, l0, h1, l1;
                        split_bf16(v0, h0, l0);
                        split_bf16(v1, h1, l1);
                        *(__nv_bfloat162*)(Yh + yrow + col) = __halves2bfloat162(h0, h1);
                        *(__nv_bfloat162*)(Yl + yrow + col) = __halves2bfloat162(l0, l1);
                    } else {
                        *(float2*)(Yf + yrow + col) = make_float2(v0, v1);
                    }
                }
            }
        }
    }
}

template <int EPI>
__global__ __launch_bounds__(256) void gemm_mma(
    const __nv_bfloat16* __restrict__ Ah, const __nv_bfloat16* __restrict__ Al,
    const __nv_bfloat16* __restrict__ Wh, const __nv_bfloat16* __restrict__ Wl,
    const float* __restrict__ bias,
    float* __restrict__ Yf,
    __nv_bfloat16* __restrict__ Yh, __nv_bfloat16* __restrict__ Yl)
{
    extern __shared__ __align__(16) char dsm[];
    gemm_body<EPI>(Ah, Al, Wh, Wl, bias, Yf, Yh, Yl,
                   blockIdx.x * 2, blockIdx.y, blockIdx.z, smem_u32(dsm));
}

__global__ __launch_bounds__(256) void gemm_wo_pair(
    const __nv_bfloat16* __restrict__ Ah0, const __nv_bfloat16* __restrict__ Al0,
    const __nv_bfloat16* __restrict__ Wh0, const __nv_bfloat16* __restrict__ Wl0,
    float* __restrict__ Y0,
    const __nv_bfloat16* __restrict__ Ah1, const __nv_bfloat16* __restrict__ Al1,
    const __nv_bfloat16* __restrict__ Wh1, const __nv_bfloat16* __restrict__ Wl1,
    float* __restrict__ Y1)
{
    extern __shared__ __align__(16) char dsm[];
    const int zz = blockIdx.z;
    const int br = zz >= CC;
    const int c = br ? zz - CC : zz;
    gemm_body<0>(br ? Ah1 : Ah0, br ? Al1 : Al0,
                 br ? Wh1 : Wh0, br ? Wl1 : Wl0,
                 nullptr, br ? Y1 : Y0, nullptr, nullptr,
                 blockIdx.x * 2, blockIdx.y, c, smem_u32(dsm));
}

// ---------------------------------------------------------------------------
// Spatial attention (R9 winner): one block per (b,s), 8 heads, 768 thr, 2 CTA/SM.
// ---------------------------------------------------------------------------
constexpr int SA_P = 260;
constexpr int SA_SMEM = (3 * CC * SA_P + HH * CC * 25) * 4;  // 94,080 B

__global__ __launch_bounds__(768, 2) void spatial_attn(
    const float* __restrict__ q, const float* __restrict__ k,
    const float* __restrict__ v, __nv_bfloat16* __restrict__ oh,
    __nv_bfloat16* __restrict__ ol)
{
    extern __shared__ float sa[];
    float* qs = sa;
    float* ks = qs + CC * SA_P;
    float* vs = ks + CC * SA_P;
    float* sc = vs + CC * SA_P;

    const int s = blockIdx.x, b = blockIdx.y;
    const int t = threadIdx.x;
    const size_t gbase = ((size_t)b * CC * SS + s) * EE;
    const size_t cstride = (size_t)SS * EE;

#pragma unroll
    for (int i = 0; i < 2; ++i) {
        const int idx = t + i * 768;
        const int row = idx >> 6, e4 = idx & 63;
        const size_t g = gbase + row * cstride + e4 * 4;
        const int so = row * SA_P + e4 * 4;
        *(float4*)(qs + so) = *(const float4*)(q + g);
        *(float4*)(ks + so) = *(const float4*)(k + g);
        *(float4*)(vs + so) = *(const float4*)(v + g);
    }
    __syncthreads();

    {
        const int h = t / 96;
        const int r = t - h * 96;
        const int cig = r >> 3, dig = r & 7;
        const int ci0 = cig * 2, di0 = dig * 3;
        const float* qb = qs + ci0 * SA_P + h * 32;
        const float* kb = ks + di0 * SA_P + h * 32;
        float a00 = 0.f, a01 = 0.f, a02 = 0.f;
        float a10 = 0.f, a11 = 0.f, a12 = 0.f;
#pragma unroll
        for (int p = 0; p < 32; ++p) {
            const float q0 = qb[p], q1 = qb[SA_P + p];
            const float k0 = kb[p], k1 = kb[SA_P + p], k2 = kb[2 * SA_P + p];
            a00 = fmaf(q0, k0, a00); a01 = fmaf(q0, k1, a01); a02 = fmaf(q0, k2, a02);
            a10 = fmaf(q1, k0, a10); a11 = fmaf(q1, k1, a11); a12 = fmaf(q1, k2, a12);
        }
        float* sr0 = sc + (h * CC + ci0) * 25 + di0;
        float* sr1 = sr0 + 25;
        sr0[0] = a00 * INV_SQRT_P; sr0[1] = a01 * INV_SQRT_P; sr0[2] = a02 * INV_SQRT_P;
        sr1[0] = a10 * INV_SQRT_P; sr1[1] = a11 * INV_SQRT_P; sr1[2] = a12 * INV_SQRT_P;
    }
    __syncthreads();

    if (t < HH * CC) {
        float* row = sc + t * 25;
        float mx = -1e30f;
#pragma unroll
        for (int d = 0; d < CC; ++d) mx = fmaxf(mx, row[d]);
        float sm = 0.f;
#pragma unroll
        for (int d = 0; d < CC; ++d) { float e = __expf(row[d] - mx); row[d] = e; sm += e; }
        const float inv = 1.f / sm;
#pragma unroll
        for (int d = 0; d < CC; ++d) row[d] *= inv;
    }
    __syncthreads();

#pragma unroll
    for (int i = 0; i < 2; ++i) {
        const int item = t + i * 768;
        const int h = item / 192;
        const int rr = item - h * 192;
        const int cc = rr >> 3, p4 = (rr & 7) * 4;
        const float* arow = sc + (h * CC + cc) * 25;
        const float* vb = vs + h * 32 + p4;
        float s0 = 0.f, s1 = 0.f, s2 = 0.f, s3 = 0.f;
#pragma unroll
        for (int d = 0; d < CC; ++d) {
            const float a = arow[d];
            const float4 vv = *(const float4*)(vb + d * SA_P);
            s0 = fmaf(a, vv.x, s0); s1 = fmaf(a, vv.y, s1);
            s2 = fmaf(a, vv.z, s2); s3 = fmaf(a, vv.w, s3);
        }
        const size_t g = gbase + cc * cstride + h * 32 + p4;
        __nv_bfloat16 h0, l0, h1, l1, h2, l2, h3, l3;
        split_bf16(s0, h0, l0); split_bf16(s1, h1, l1);
        split_bf16(s2, h2, l2); split_bf16(s3, h3, l3);
        *(__nv_bfloat162*)(oh + g)     = __halves2bfloat162(h0, h1);
        *(__nv_bfloat162*)(oh + g + 2) = __halves2bfloat162(h2, h3);
        *(__nv_bfloat162*)(ol + g)     = __halves2bfloat162(l0, l1);
        *(__nv_bfloat162*)(ol + g + 2) = __halves2bfloat162(l2, l3);
    }
}

// ---------------------------------------------------------------------------
// Temporal attention v3 — tensor-core flash-style (R12 winner).
// ---------------------------------------------------------------------------
constexpr int TQT_HI = 0;
constexpr int TQT_LO = 128 * GP;             // 10240
constexpr int TKT_HI = 2 * 128 * GP;         // 20480
constexpr int TKT_LO = 3 * 128 * GP;         // 30720
constexpr int TVS_HI = 4 * 128 * GP;         // 40960
constexpr int TVP = 272;                     // V^T pitch (bytes)
constexpr int TVS_LO = TVS_HI + 32 * TVP;    // 49664
constexpr int TEMP_SMEM_BYTES = TVS_LO + 32 * TVP;  // 58368

__global__ __launch_bounds__(256, 2) void temporal_attn(
    const float* __restrict__ q, const float* __restrict__ k,
    const float* __restrict__ v, __nv_bfloat16* __restrict__ oh,
    __nv_bfloat16* __restrict__ ol)
{
    extern __shared__ __align__(16) char tsm[];
    const uint32_t sb = smem_u32(tsm);
    const int c = blockIdx.x, h = blockIdx.y, b = blockIdx.z;
    const int tid = threadIdx.x;
    const int wid = tid >> 5, lane = tid & 31;
    const size_t base = (((size_t)b * CC + c) * SS) * EE + h * PP;

#pragma unroll
    for (int i = 0; i < 4; ++i) {
        const int idx = tid + i * 256;
        const int row = idx >> 3, p4 = (idx & 7) * 4;
        const size_t g = base + (size_t)row * EE + p4;
        {
            float4 vq = *(const float4*)(q + g);
            __nv_bfloat16 hh[4], ll[4];
            split_bf16(vq.x, hh[0], ll[0]); split_bf16(vq.y, hh[1], ll[1]);
            split_bf16(vq.z, hh[2], ll[2]); split_bf16(vq.w, hh[3], ll[3]);
            uint2 hp, lp;
            ((__nv_bfloat162*)&hp)[0] = __halves2bfloat162(hh[0], hh[1]);
            ((__nv_bfloat162*)&hp)[1] = __halves2bfloat162(hh[2], hh[3]);
            ((__nv_bfloat162*)&lp)[0] = __halves2bfloat162(ll[0], ll[1]);
            ((__nv_bfloat162*)&lp)[1] = __halves2bfloat162(ll[2], ll[3]);
            *(uint2*)(tsm + TQT_HI + row * GP + p4 * 2) = hp;
            *(uint2*)(tsm + TQT_LO + row * GP + p4 * 2) = lp;
        }
        {
            float4 vk = *(const float4*)(k + g);
            __nv_bfloat16 hh[4], ll[4];
            split_bf16(vk.x, hh[0], ll[0]); split_bf16(vk.y, hh[1], ll[1]);
            split_bf16(vk.z, hh[2], ll[2]); split_bf16(vk.w, hh[3], ll[3]);
            uint2 hp, lp;
            ((__nv_bfloat162*)&hp)[0] = __halves2bfloat162(hh[0], hh[1]);
            ((__nv_bfloat162*)&hp)[1] = __halves2bfloat162(hh[2], hh[3]);
            ((__nv_bfloat162*)&lp)[0] = __halves2bfloat162(ll[0], ll[1]);
            ((__nv_bfloat162*)&lp)[1] = __halves2bfloat162(ll[2], ll[3]);
            *(uint2*)(tsm + TKT_HI + row * GP + p4 * 2) = hp;
            *(uint2*)(tsm + TKT_LO + row * GP + p4 * 2) = lp;
        }
        {
            float4 vv = *(const float4*)(v + g);
            float vf[4] = {vv.x, vv.y, vv.z, vv.w};
#pragma unroll
            for (int j = 0; j < 4; ++j) {
                __nv_bfloat16 hi, lo;
                split_bf16(vf[j], hi, lo);
                *(__nv_bfloat16*)(tsm + TVS_HI + (p4 + j) * TVP + row * 2) = hi;
                *(__nv_bfloat16*)(tsm + TVS_LO + (p4 + j) * TVP + row * 2) = lo;
            }
        }
    }
    __syncthreads();

    const int g2 = lane >> 3, lr = lane & 7;

    float sacc[16][4];
#pragma unroll
    for (int nj = 0; nj < 16; ++nj)
#pragma unroll
        for (int r = 0; r < 4; ++r) sacc[nj][r] = 0.f;

#pragma unroll
    for (int pass = 0; pass < 3; ++pass) {
        const uint32_t Ab = sb + (pass == 2 ? TQT_LO : TQT_HI);
        const uint32_t Bb = sb + (pass == 1 ? TKT_LO : TKT_HI);
#pragma unroll
        for (int k16 = 0; k16 < 2; ++k16) {
            uint32_t afr[4];
            {
                const int row = wid * 16 + ((g2 & 1) << 3) + lr;
                const uint32_t addr = Ab + row * GP + (k16 * 2 + (g2 >> 1)) * 16;
                ldsm_x4(afr[0], afr[1], afr[2], afr[3], addr);
            }
#pragma unroll
            for (int ni = 0; ni < 8; ++ni) {
                uint32_t bfr[4];
                const int row = ni * 16 + ((g2 >> 1) << 3) + lr;
                const uint32_t addr = Bb + row * GP + (k16 * 2 + (g2 & 1)) * 16;
                ldsm_x4(bfr[0], bfr[1], bfr[2], bfr[3], addr);
                mma_bf16(sacc[ni * 2 + 0], afr, bfr[0], bfr[1]);
                mma_bf16(sacc[ni * 2 + 1], afr, bfr[2], bfr[3]);
            }
        }
    }

#pragma unroll
    for (int nj = 0; nj < 16; ++nj)
#pragma unroll
        for (int r = 0; r < 4; ++r) sacc[nj][r] *= INV_SQRT_P;

    float mx0 = -1e30f, mx1 = -1e30f;
#pragma unroll
    for (int nj = 0; nj < 16; ++nj) {
        mx0 = fmaxf(mx0, fmaxf(sacc[nj][0], sacc[nj][1]));
        mx1 = fmaxf(mx1, fmaxf(sacc[nj][2], sacc[nj][3]));
    }
    mx0 = fmaxf(mx0, __shfl_xor_sync(0xffffffffu, mx0, 1));
    mx0 = fmaxf(mx0, __shfl_xor_sync(0xffffffffu, mx0, 2));
    mx1 = fmaxf(mx1, __shfl_xor_sync(0xffffffffu, mx1, 1));
    mx1 = fmaxf(mx1, __shfl_xor_sync(0xffffffffu, mx1, 2));

    float sum0 = 0.f, sum1 = 0.f;
#pragma unroll
    for (int nj = 0; nj < 16; ++nj) {
        sacc[nj][0] = __expf(sacc[nj][0] - mx0);
        sacc[nj][1] = __expf(sacc[nj][1] - mx0);
        sacc[nj][2] = __expf(sacc[nj][2] - mx1);
        sacc[nj][3] = __expf(sacc[nj][3] - mx1);
        sum0 += sacc[nj][0] + sacc[nj][1];
        sum1 += sacc[nj][2] + sacc[nj][3];
    }
    sum0 += __shfl_xor_sync(0xffffffffu, sum0, 1);
    sum0 += __shfl_xor_sync(0xffffffffu, sum0, 2);
    sum1 += __shfl_xor_sync(0xffffffffu, sum1, 1);
    sum1 += __shfl_xor_sync(0xffffffffu, sum1, 2);
    const float inv0 = 1.f / sum0, inv1 = 1.f / sum1;
#pragma unroll
    for (int nj = 0; nj < 16; ++nj) {
        sacc[nj][0] *= inv0;
        sacc[nj][1] *= inv0;
        sacc[nj][2] *= inv1;
        sacc[nj][3] *= inv1;
    }

    float oacc[4][4];
#pragma unroll
    for (int nj = 0; nj < 4; ++nj)
#pragma unroll
        for (int r = 0; r < 4; ++r) oacc[nj][r] = 0.f;

#pragma unroll
    for (int pass = 0; pass < 3; ++pass) {
        const uint32_t Bb = sb + (pass == 1 ? TVS_LO : TVS_HI);
#pragma unroll
        for (int ki = 0; ki < 8; ++ki) {
            uint32_t a[4];
            if (pass <= 1) {
                a[0] = pack_bf16x2(sacc[2 * ki][0],     sacc[2 * ki][1]);
                a[1] = pack_bf16x2(sacc[2 * ki][2],     sacc[2 * ki][3]);
                a[2] = pack_bf16x2(sacc[2 * ki + 1][0], sacc[2 * ki + 1][1]);
                a[3] = pack_bf16x2(sacc[2 * ki + 1][2], sacc[2 * ki + 1][3]);
            } else {
                a[0] = pack_bf16x2(bf16_lo_res(sacc[2 * ki][0]),     bf16_lo_res(sacc[2 * ki][1]));
                a[1] = pack_bf16x2(bf16_lo_res(sacc[2 * ki][2]),     bf16_lo_res(sacc[2 * ki][3]));
                a[2] = pack_bf16x2(bf16_lo_res(sacc[2 * ki + 1][0]), bf16_lo_res(sacc[2 * ki + 1][1]));
                a[3] = pack_bf16x2(bf16_lo_res(sacc[2 * ki + 1][2]), bf16_lo_res(sacc[2 * ki + 1][3]));
            }
#pragma unroll
            for (int half = 0; half < 2; ++half) {
                uint32_t bfr[4];
                const int row = half * 16 + ((g2 >> 1) << 3) + lr;
                const uint32_t addr = Bb + row * TVP + (ki * 2 + (g2 & 1)) * 16;
                ldsm_x4(bfr[0], bfr[1], bfr[2], bfr[3], addr);
                mma_bf16(oacc[half * 2 + 0], a, bfr[0], bfr[1]);
                mma_bf16(oacc[half * 2 + 1], a, bfr[2], bfr[3]);
            }
        }
    }

    const int r0 = wid * 16 + (lane >> 2);
    const int r1 = r0 + 8;
#pragma unroll
    for (int nj = 0; nj < 4; ++nj) {
        const int col = nj * 8 + (lane & 3) * 2;
        const size_t g0 = base + (size_t)r0 * EE + col;
        const size_t g1 = base + (size_t)r1 * EE + col;
        __nv_bfloat16 h0, l0, h1, l1;
        split_bf16(oacc[nj][0], h0, l0);
        split_bf16(oacc[nj][1], h1, l1);
        *(__nv_bfloat162*)(oh + g0) = __halves2bfloat162(h0, h1);
        *(__nv_bfloat162*)(ol + g0) = __halves2bfloat162(l0, l1);
        split_bf16(oacc[nj][2], h0, l0);
        split_bf16(oacc[nj][3], h1, l1);
        *(__nv_bfloat162*)(oh + g1) = __halves2bfloat162(h0, h1);
        *(__nv_bfloat162*)(ol + g1) = __halves2bfloat162(l0, l1);
    }
}

// ---------------------------------------------------------------------------
// LayerNorm kernels — warp-per-row.
// ---------------------------------------------------------------------------
__device__ __forceinline__ float warp_sum(float v) {
#pragma unroll
    for (int off = 16; off > 0; off >>= 1)
        v += __shfl_xor_sync(0xffffffffu, v, off);
    return v;
}

__global__ __launch_bounds__(256) void dual_ln(
    const float* __restrict__ x, const float* __restrict__ a,
    const float* __restrict__ b2, const float* __restrict__ g,
    const float* __restrict__ beta, float* __restrict__ out,
    __nv_bfloat16* __restrict__ oh, __nv_bfloat16* __restrict__ ol)
{
    const int warp = threadIdx.x >> 5, lane = threadIdx.x & 31;
    const int row = blockIdx.x * 8 + warp;
    const size_t base = (size_t)row * EE;
    const int e0 = lane * 4, e1 = 128 + lane * 4;

    float4 x0 = *(const float4*)(x + base + e0);
    float4 x1 = *(const float4*)(x + base + e1);
    float4 a0 = *(const float4*)(a + base + e0);
    float4 a1 = *(const float4*)(a + base + e1);
    float4 b0 = *(const float4*)(b2 + base + e0);
    float4 b1 = *(const float4*)(b2 + base + e1);

    float v1[8] = {x0.x + a0.x, x0.y + a0.y, x0.z + a0.z, x0.w + a0.w,
                   x1.x + a1.x, x1.y + a1.y, x1.z + a1.z, x1.w + a1.w};
    float v2[8] = {x0.x + b0.x, x0.y + b0.y, x0.z + b0.z, x0.w + b0.w,
                   x1.x + b1.x, x1.y + b1.y, x1.z + b1.z, x1.w + b1.w};

    float s1 = 0.f, q1 = 0.f, s2 = 0.f, q2 = 0.f;
#pragma unroll
    for (int j = 0; j < 8; ++j) {
        s1 += v1[j]; q1 = fmaf(v1[j], v1[j], q1);
        s2 += v2[j]; q2 = fmaf(v2[j], v2[j], q2);
    }
    s1 = warp_sum(s1); q1 = warp_sum(q1);
    s2 = warp_sum(s2); q2 = warp_sum(q2);

    const float invE = 1.f / (float)EE;
    const float m1 = s1 * invE, m2 = s2 * invE;
    const float r1 = rsqrtf(fmaxf(q1 * invE - m1 * m1, 0.f) + LN_EPS);
    const float r2 = rsqrtf(fmaxf(q2 * invE - m2 * m2, 0.f) + LN_EPS);

    float4 g0 = *(const float4*)(g + e0);
    float4 g1 = *(const float4*)(g + e1);
    float4 t0 = *(const float4*)(beta + e0);
    float4 t1 = *(const float4*)(beta + e1);
    float gg[8] = {g0.x, g0.y, g0.z, g0.w, g1.x, g1.y, g1.z, g1.w};
    float bt[8] = {t0.x, t0.y, t0.z, t0.w, t1.x, t1.y, t1.z, t1.w};

    float o[8];
#pragma unroll
    for (int j = 0; j < 8; ++j)
        o[j] = (v1[j] - m1) * r1 * gg[j] + bt[j]
             + (v2[j] - m2) * r2 * gg[j] + bt[j];

    *(float4*)(out + base + e0) = make_float4(o[0], o[1], o[2], o[3]);
    *(float4*)(out + base + e1) = make_float4(o[4], o[5], o[6], o[7]);

    __nv_bfloat16 hh[8], ll[8];
#pragma unroll
    for (int j = 0; j < 8; ++j) split_bf16(o[j], hh[j], ll[j]);
    *(__nv_bfloat162*)(oh + base + e0)     = __halves2bfloat162(hh[0], hh[1]);
    *(__nv_bfloat162*)(oh + base + e0 + 2) = __halves2bfloat162(hh[2], hh[3]);
    *(__nv_bfloat162*)(oh + base + e1)     = __halves2bfloat162(hh[4], hh[5]);
    *(__nv_bfloat162*)(oh + base + e1 + 2) = __halves2bfloat162(hh[6], hh[7]);
    *(__nv_bfloat162*)(ol + base + e0)     = __halves2bfloat162(ll[0], ll[1]);
    *(__nv_bfloat162*)(ol + base + e0 + 2) = __halves2bfloat162(ll[2], ll[3]);
    *(__nv_bfloat162*)(ol + base + e1)     = __halves2bfloat162(ll[4], ll[5]);
    *(__nv_bfloat162*)(ol + base + e1 + 2) = __halves2bfloat162(ll[6], ll[7]);
}

__global__ __launch_bounds__(256) void final_ln(
    const float* __restrict__ a, const float* __restrict__ f,
    const float* __restrict__ g, const float* __restrict__ beta,
    float* __restrict__ out)
{
    const int warp = threadIdx.x >> 5, lane = threadIdx.x & 31;
    const int row = blockIdx.x * 8 + warp;
    const size_t base = (size_t)row * EE;
    const int e0 = lane * 4, e1 = 128 + lane * 4;

    float4 a0 = *(const float4*)(a + base + e0);
    float4 a1 = *(const float4*)(a + base + e1);
    float4 f0 = *(const float4*)(f + base + e0);
    float4 f1 = *(const float4*)(f + base + e1);

    float v[8] = {a0.x + f0.x, a0.y + f0.y, a0.z + f0.z, a0.w + f0.w,
                  a1.x + f1.x, a1.y + f1.y, a1.z + f1.z, a1.w + f1.w};

    float s = 0.f, q = 0.f;
#pragma unroll
    for (int j = 0; j < 8; ++j) { s += v[j]; q = fmaf(v[j], v[j], q); }
    s = warp_sum(s); q = warp_sum(q);

    const float invE = 1.f / (float)EE;
    const float m = s * invE;
    const float r = rsqrtf(fmaxf(q * invE - m * m, 0.f) + LN_EPS);

    float4 g0 = *(const float4*)(g + e0);
    float4 g1 = *(const float4*)(g + e1);
    float4 t0 = *(const float4*)(beta + e0);
    float4 t1 = *(const float4*)(beta + e1);
    float gg[8] = {g0.x, g0.y, g0.z, g0.w, g1.x, g1.y, g1.z, g1.w};
    float bt[8] = {t0.x, t0.y, t0.z, t0.w, t1.x, t1.y, t1.z, t1.w};

    float o[8];
#pragma unroll
    for (int j = 0; j < 8; ++j) o[j] = (v[j] - m) * r * gg[j] + bt[j];
    *(float4*)(out + base + e0) = make_float4(o[0], o[1], o[2], o[3]);
    *(float4*)(out + base + e1) = make_float4(o[4], o[5], o[6], o[7]);
}

// ---------------------------------------------------------------------------
// kernel_launch
// ---------------------------------------------------------------------------
extern "C" void kernel_launch(void* const* d_in, const int* in_sizes, int n_in,
                              void* d_out, int out_size)
{
    const float* x    = (const float*)d_in[0];
    const float* ln_g = (const float*)d_in[9];
    const float* ln_b = (const float*)d_in[10];
    const float* ff_b1 = (const float*)d_in[12];
    const float* ff_b2 = (const float*)d_in[14];
    float* out = (float*)d_out;

    float *qs, *ks, *vs, *qt, *kt, *vt, *spat, *temp, *attn, *ffo;
    __nv_bfloat16 *ah, *al, *hh, *hl, *wh, *wl;
    cudaGetSymbolAddress((void**)&qs,   g_qs);
    cudaGetSymbolAddress((void**)&ks,   g_ks);
    cudaGetSymbolAddress((void**)&vs,   g_vs);
    cudaGetSymbolAddress((void**)&qt,   g_qt);
    cudaGetSymbolAddress((void**)&kt,   g_kt);
    cudaGetSymbolAddress((void**)&vt,   g_vt);
    cudaGetSymbolAddress((void**)&spat, g_spat);
    cudaGetSymbolAddress((void**)&temp, g_temp);
    cudaGetSymbolAddress((void**)&attn, g_attn);
    cudaGetSymbolAddress((void**)&ffo,  g_ffo);
    cudaGetSymbolAddress((void**)&ah, g_ah);
    cudaGetSymbolAddress((void**)&al, g_al);
    cudaGetSymbolAddress((void**)&hh, g_hh);
    cudaGetSymbolAddress((void**)&hl, g_hl);
    cudaGetSymbolAddress((void**)&wh, g_wh);
    cudaGetSymbolAddress((void**)&wl, g_wl);

    cudaFuncSetAttribute(gemm_qkv6,   cudaFuncAttributeMaxDynamicSharedMemorySize, QKV_SMEM);
    cudaFuncSetAttribute(gemm_mma<1>, cudaFuncAttributeMaxDynamicSharedMemorySize, GEMM_SMEM);
    cudaFuncSetAttribute(gemm_mma<2>, cudaFuncAttributeMaxDynamicSharedMemorySize, GEMM_SMEM);
    cudaFuncSetAttribute(gemm_wo_pair, cudaFuncAttributeMaxDynamicSharedMemorySize, GEMM_SMEM);
    cudaFuncSetAttribute(spatial_attn, cudaFuncAttributeMaxDynamicSharedMemorySize, SA_SMEM);
    cudaFuncSetAttribute(temporal_attn, cudaFuncAttributeMaxDynamicSharedMemorySize, TEMP_SMEM_BYTES);

    // ---- weight conversion ----
    WPtrs wp;
    wp.p[0] = (const float*)d_in[1];
    wp.p[1] = (const float*)d_in[2];
    wp.p[2] = (const float*)d_in[3];
    wp.p[3] = (const float*)d_in[4];
    wp.p[4] = (const float*)d_in[5];
    wp.p[5] = (const float*)d_in[6];
    wp.p[6] = (const float*)d_in[7];
    wp.p[7] = (const float*)d_in[8];
    wp.p[8] = (const float*)d_in[11];
    wp.p[9] = (const float*)d_in[13];
    convert_weights_t<<<dim3(64, CC, NW), 256>>>(wp, wh, wl);

    // ---- fused q/k/v projections (x split in-kernel; N=256 blocks, 512 thr) ----
    Out6 o6;
    o6.y[0] = qs; o6.y[1] = ks; o6.y[2] = vs;
    o6.y[3] = qt; o6.y[4] = kt; o6.y[5] = vt;
    gemm_qkv6<<<dim3(BB, 1, CC), 512, QKV_SMEM>>>(x, wh, wl, o6);

    // ---- attentions ----
    spatial_attn<<<dim3(SS, BB), 768, SA_SMEM>>>(qs, ks, vs, ah, al);
    temporal_attn<<<dim3(CC, HH, BB), 256, TEMP_SMEM_BYTES>>>(qt, kt, vt, hh, hl);

    // ---- output projections (merged dual launch, M=256 blocks) ----
    gemm_wo_pair<<<dim3(BB / 2, 2, 2 * CC), 256, GEMM_SMEM>>>(
        ah, al, wh + 3*(size_t)WELEMS, wl + 3*(size_t)WELEMS, spat,
        hh, hl, wh + 7*(size_t)WELEMS, wl + 7*(size_t)WELEMS, temp);

    // ---- residual + dual LN (emits attn fp32 + bf16 pair) ----
    dual_ln<<<NROWS / 8, 256>>>(x, spat, temp, ln_g, ln_b, attn, ah, al);

    // ---- per-joint FF + final LN ----
    gemm_mma<1><<<dim3(BB / 2, 2, CC), 256, GEMM_SMEM>>>(ah, al, wh + 8*(size_t)WELEMS, wl + 8*(size_t)WELEMS, ff_b1, nullptr, hh, hl);
    gemm_mma<2><<<dim3(BB / 2, 2, CC), 256, GEMM_SMEM>>>(hh, hl, wh + 9*(size_t)WELEMS, wl + 9*(size_t)WELEMS, ff_b2, ffo, nullptr, nullptr);
    final_ln<<<NROWS / 8, 256>>>(attn, ffo, ln_g, ln_b, out);
}

// round 15
// speedup vs baseline: 1.0183x; 1.0183x over previous
#include <cuda_runtime.h>
#include <cuda_bf16.h>
#include <cstdint>
#include <cstddef>

// Problem dims
constexpr int BB = 16, CC = 24, SS = 128, EE = 256, HH = 8, PP = 32;
constexpr int NTOT  = BB * CC * SS * EE;     // 12,582,912
constexpr int NROWS = BB * CC * SS;          // 49,152
constexpr int WELEMS = CC * EE * EE;         // 1,572,864 per weight
constexpr int NW = 10;
constexpr float LN_EPS = 1e-6f;
constexpr float INV_SQRT_P = 0.17677669529663687f;

// ---------------------------------------------------------------------------
// Device scratch
// ---------------------------------------------------------------------------
__device__ float g_qs[NTOT], g_ks[NTOT], g_vs[NTOT];
__device__ float g_qt[NTOT], g_kt[NTOT], g_vt[NTOT];
__device__ float g_spat[NTOT], g_temp[NTOT], g_attn[NTOT], g_ffo[NTOT];
__device__ __align__(16) __nv_bfloat16 g_ah[NTOT], g_al[NTOT];   // spatial-out / attn pair
__device__ __align__(16) __nv_bfloat16 g_hh[NTOT], g_hl[NTOT];   // temporal-out / ff hidden pair
__device__ __align__(16) __nv_bfloat16 g_wh[NW * WELEMS], g_wl[NW * WELEMS];

// ---------------------------------------------------------------------------
// PTX helpers (baseline ISA only)
// ---------------------------------------------------------------------------
__device__ __forceinline__ uint32_t smem_u32(const void* p) {
    uint32_t a;
    asm("{ .reg .u64 t; cvta.to.shared.u64 t, %1; cvt.u32.u64 %0, t; }"
        : "=r"(a) : "l"(p));
    return a;
}
__device__ __forceinline__ void cp_async16(uint32_t smem, const void* gmem) {
    asm volatile("cp.async.cg.shared.global [%0], [%1], 16;"
                 :: "r"(smem), "l"(gmem));
}
__device__ __forceinline__ void cp_commit() {
    asm volatile("cp.async.commit_group;");
}
template <int N>
__device__ __forceinline__ void cp_wait() {
    asm volatile("cp.async.wait_group %0;" :: "n"(N) : "memory");
}
__device__ __forceinline__ void ldsm_x4(uint32_t& r0, uint32_t& r1,
                                        uint32_t& r2, uint32_t& r3, uint32_t addr) {
    asm volatile("ldmatrix.sync.aligned.m8n8.x4.shared.b16 {%0,%1,%2,%3}, [%4];"
                 : "=r"(r0), "=r"(r1), "=r"(r2), "=r"(r3) : "r"(addr));
}
__device__ __forceinline__ void mma_bf16(float* d, const uint32_t* a,
                                         uint32_t b0, uint32_t b1) {
    asm volatile(
        "mma.sync.aligned.m16n8k16.row.col.f32.bf16.bf16.f32 "
        "{%0,%1,%2,%3}, {%4,%5,%6,%7}, {%8,%9}, {%0,%1,%2,%3};"
        : "+f"(d[0]), "+f"(d[1]), "+f"(d[2]), "+f"(d[3])
        : "r"(a[0]), "r"(a[1]), "r"(a[2]), "r"(a[3]), "r"(b0), "r"(b1));
}
// packed f32x2
__device__ __forceinline__ unsigned long long pack2(float v) {
    unsigned long long r;
    asm("mov.b64 %0, {%1, %1};" : "=l"(r) : "f"(v));
    return r;
}
__device__ __forceinline__ void fma2(unsigned long long& d,
                                     unsigned long long a, unsigned long long b) {
    asm("fma.rn.f32x2 %0, %1, %2, %0;" : "+l"(d) : "l"(a), "l"(b));
}
__device__ __forceinline__ float2 unpack2(unsigned long long v) {
    float2 f;
    asm("mov.b64 {%0, %1}, %2;" : "=f"(f.x), "=f"(f.y) : "l"(v));
    return f;
}

// ---------------------------------------------------------------------------
// bf16 hi/lo split helpers
// ---------------------------------------------------------------------------
__device__ __forceinline__ void split_bf16(float x, __nv_bfloat16& h, __nv_bfloat16& l) {
    h = __float2bfloat16_rn(x);
    l = __float2bfloat16_rn(x - __bfloat162float(h));
}
__device__ __forceinline__ uint32_t pack_bf16x2(float a, float b) {
    __nv_bfloat162 t = __halves2bfloat162(__float2bfloat16_rn(a), __float2bfloat16_rn(b));
    return *(uint32_t*)&t;
}
__device__ __forceinline__ float bf16_lo_res(float x) {
    return x - __bfloat162float(__float2bfloat16_rn(x));
}

// ---------------------------------------------------------------------------
// Weight conversion, coalesced: 32x32 (e,f) tiles via smem transpose.
// ---------------------------------------------------------------------------
struct WPtrs { const float* p[NW]; };

__global__ __launch_bounds__(256) void convert_weights_t(
    WPtrs wp, __nv_bfloat16* __restrict__ wh, __nv_bfloat16* __restrict__ wl)
{
    __shared__ float tile[32][33];
    const int w = blockIdx.z, c = blockIdx.y;
    const int eb = blockIdx.x & 7, fb = blockIdx.x >> 3;
    const int mode = (w == 3 || w >= 7) ? 0 : (w == 0 ? 1 : (w <= 2 ? 2 : 3));
    const int t = threadIdx.x;
    const int col = t & 31, r0 = t >> 5;
    const float* W = wp.p[w];

#pragma unroll
    for (int i = 0; i < 4; ++i) {
        const int row = r0 + i * 8;
        float v;
        if (mode == 0) {
            const int e = eb * 32 + row, f = fb * 32 + col;
            v = W[((size_t)c * EE + e) * EE + f];
        } else if (mode == 1) {
            const int f = fb * 32 + row, e = eb * 32 + col;
            const int h = fb, p = f & 31;
            v = W[(((size_t)h * CC + c) * PP + p) * EE + e];
        } else if (mode == 2) {
            const int e = eb * 32 + row, p = col, h = fb;
            v = W[((size_t)h * EE + e) * PP + p];
        } else {
            const int e = eb * 32 + row, p = col, h = fb;
            v = W[(((size_t)h * CC + c) * EE + e) * PP + p];
        }
        tile[row][col] = v;
    }
    __syncthreads();

#pragma unroll
    for (int i = 0; i < 4; ++i) {
        const int fr = r0 + i * 8;
        const int f = fb * 32 + fr;
        const int e = eb * 32 + col;
        const float v = (mode == 1) ? tile[fr][col] : tile[col][fr];
        __nv_bfloat16 hi, lo;
        split_bf16(v, hi, lo);
        const size_t o = (size_t)w * WELEMS + ((size_t)c << 16) + (size_t)f * EE + e;
        wh[o] = hi;
        wl[o] = lo;
    }
}

// ---------------------------------------------------------------------------
// Fused QKVx6 GEMM (R13 winner): A resident (in-kernel split), block
// M=128 x N=256, 8 warps (256 thr) with 64x64 tiles, 48 B-stages double-buf.
// ---------------------------------------------------------------------------
constexpr int AP = 528;
constexpr int QA_HI = 0;
constexpr int QA_LO = 128 * AP;
constexpr int QB0   = 2 * 128 * AP;            // 135168
constexpr int GP = 80;
constexpr int QB_LO  = 256 * GP;               // 20480 (within stage)
constexpr int QB_STG = 2 * 256 * GP;           // 40960
constexpr int QKV_SMEM = QB0 + 2 * QB_STG;     // 217088

struct Out6 { float* y[6]; };

__global__ __launch_bounds__(256) void gemm_qkv6(
    const float* __restrict__ x,
    const __nv_bfloat16* __restrict__ whB, const __nv_bfloat16* __restrict__ wlB,
    Out6 outs)
{
    extern __shared__ __align__(16) char dsm[];
    const uint32_t sbase = smem_u32(dsm);
    const int tid = threadIdx.x;
    const int wid = tid >> 5, lane = tid & 31;
    const int b = blockIdx.x, c = blockIdx.z;

    const size_t abase = ((size_t)b * CC + c) * SS * EE;

    auto issueB = [&](int stage) {
        const int w = stage >> 3, kb = (stage & 7) * 32;
        const int wg = w + (w >= 3);           // 0,1,2,4,5,6
        const __nv_bfloat16* Wh = whB + (size_t)wg * WELEMS + ((size_t)c << 16);
        const __nv_bfloat16* Wl = wlB + (size_t)wg * WELEMS + ((size_t)c << 16);
        const uint32_t sb = sbase + QB0 + (stage & 1) * QB_STG;
#pragma unroll
        for (int j = 0; j < 4; ++j) {
            const int t2 = tid + j * 256;      // 0..1023 = 256 rows x 4 chunks
            const int row = t2 >> 2, ch = t2 & 3;
            const size_t goff = (size_t)row * EE + kb + ch * 8;
            const uint32_t so = row * GP + ch * 16;
            cp_async16(sb + so, Wh + goff);
            cp_async16(sb + QB_LO + so, Wl + goff);
        }
    };
    issueB(0); cp_commit();
    issueB(1); cp_commit();

    // ---- load A from fp32 x, split to bf16 hi/lo in smem ----
#pragma unroll
    for (int i = 0; i < 16; ++i) {
        const int t2 = tid + i * 256;
        const int row = t2 >> 5, ch = t2 & 31;
        const float* src = x + abase + (size_t)row * EE + ch * 8;
        float4 v0 = *(const float4*)src;
        float4 v1 = *(const float4*)(src + 4);
        float vv[8] = {v0.x, v0.y, v0.z, v0.w, v1.x, v1.y, v1.z, v1.w};
        __nv_bfloat16 h[8], l[8];
#pragma unroll
        for (int j = 0; j < 8; ++j) split_bf16(vv[j], h[j], l[j]);
        uint4 hp, lp;
        ((__nv_bfloat162*)&hp)[0] = __halves2bfloat162(h[0], h[1]);
        ((__nv_bfloat162*)&hp)[1] = __halves2bfloat162(h[2], h[3]);
        ((__nv_bfloat162*)&hp)[2] = __halves2bfloat162(h[4], h[5]);
        ((__nv_bfloat162*)&hp)[3] = __halves2bfloat162(h[6], h[7]);
        ((__nv_bfloat162*)&lp)[0] = __halves2bfloat162(l[0], l[1]);
        ((__nv_bfloat162*)&lp)[1] = __halves2bfloat162(l[2], l[3]);
        ((__nv_bfloat162*)&lp)[2] = __halves2bfloat162(l[4], l[5]);
        ((__nv_bfloat162*)&lp)[3] = __halves2bfloat162(l[6], l[7]);
        const uint32_t so = row * AP + ch * 16;
        *(uint4*)(dsm + QA_HI + so) = hp;
        *(uint4*)(dsm + QA_LO + so) = lp;
    }

    const int wm = wid & 1, wn = wid >> 1;     // 2 m-groups x 4 n-groups (64x64)
    const int g = lane >> 3, lr = lane & 7;

    for (int w = 0; w < 6; ++w) {
        float acc[4][8][4];
#pragma unroll
        for (int mi = 0; mi < 4; ++mi)
#pragma unroll
            for (int nj = 0; nj < 8; ++nj)
#pragma unroll
                for (int r = 0; r < 4; ++r) acc[mi][nj][r] = 0.f;

        for (int kc = 0; kc < 8; ++kc) {
            const int stage = w * 8 + kc;
            cp_wait<1>();
            __syncthreads();
            const uint32_t Bst = sbase + QB0 + (stage & 1) * QB_STG;

#pragma unroll
            for (int pass = 0; pass < 3; ++pass) {
                const uint32_t Ab = sbase + (pass == 2 ? QA_LO : QA_HI);
                const uint32_t Bb = Bst + (pass == 1 ? QB_LO : 0);
#pragma unroll
                for (int k16 = 0; k16 < 2; ++k16) {
                    uint32_t afr[4][4];
#pragma unroll
                    for (int mi = 0; mi < 4; ++mi) {
                        const int row = wm * 64 + mi * 16 + ((g & 1) << 3) + lr;
                        const uint32_t addr =
                            Ab + row * AP + (kc * 4 + k16 * 2 + (g >> 1)) * 16;
                        ldsm_x4(afr[mi][0], afr[mi][1], afr[mi][2], afr[mi][3], addr);
                    }
                    uint32_t bfr[4][4];
#pragma unroll
                    for (int ni = 0; ni < 4; ++ni) {
                        const int row = wn * 64 + ni * 16 + ((g >> 1) << 3) + lr;
                        const uint32_t addr = Bb + row * GP + (k16 * 2 + (g & 1)) * 16;
                        ldsm_x4(bfr[ni][0], bfr[ni][1], bfr[ni][2], bfr[ni][3], addr);
                    }
#pragma unroll
                    for (int mi = 0; mi < 4; ++mi)
#pragma unroll
                        for (int nj = 0; nj < 8; ++nj)
                            mma_bf16(acc[mi][nj], afr[mi],
                                     bfr[nj >> 1][(nj & 1) * 2],
                                     bfr[nj >> 1][(nj & 1) * 2 + 1]);
                }
            }
            __syncthreads();
            if (stage + 2 < 48) issueB(stage + 2);
            cp_commit();
        }

        float* Yf = outs.y[w];
#pragma unroll
        for (int mi = 0; mi < 4; ++mi)
#pragma unroll
            for (int rr = 0; rr < 2; ++rr) {
                const int m = wm * 64 + mi * 16 + (lane >> 2) + rr * 8;
                const size_t yrow = abase + (size_t)m * EE;
#pragma unroll
                for (int nj = 0; nj < 8; ++nj) {
                    const int colo = wn * 64 + nj * 8 + (lane & 3) * 2;
                    *(float2*)(Yf + yrow + colo) =
                        make_float2(acc[mi][nj][rr * 2 + 0], acc[mi][nj][rr * 2 + 1]);
                }
            }
    }
}

// ---------------------------------------------------------------------------
// Generic HMMA GEMM body v3: 256(M)x128(N) block (2 b-slices), 64x64 warp
// tiles, THREE-stage cp.async pipeline (184 KB smem, 1 CTA/SM).
// ---------------------------------------------------------------------------
constexpr int T_A_HI = 0;
constexpr int T_A_LO = 256 * GP;              // 20480
constexpr int T_B_HI = 2 * 256 * GP;          // 40960
constexpr int T_B_LO = T_B_HI + 128 * GP;     // 51200
constexpr int STAGE  = T_B_LO + 128 * GP;     // 61440
constexpr int GEMM_SMEM = 3 * STAGE;          // 184320

template <int EPI>
__device__ __forceinline__ void gemm_body(
    const __nv_bfloat16* __restrict__ Ah, const __nv_bfloat16* __restrict__ Al,
    const __nv_bfloat16* __restrict__ Wh, const __nv_bfloat16* __restrict__ Wl,
    const float* __restrict__ bias,
    float* __restrict__ Yf,
    __nv_bfloat16* __restrict__ Yh, __nv_bfloat16* __restrict__ Yl,
    int b0, int nb, int c, uint32_t sbase)
{
    const int tid = threadIdx.x;
    const int wid = tid >> 5, lane = tid & 31;

    const size_t abase0 = ((size_t)b0 * CC + c) * SS * EE;
    const size_t bstride = (size_t)CC * SS * EE;
    const size_t wbase = (size_t)c * EE * EE + (size_t)nb * 128 * EE;

    auto issue = [&](int stg) {
        const int kb = stg * 32;
        const uint32_t sb = sbase + (stg % 3) * STAGE;
#pragma unroll
        for (int j = 0; j < 4; ++j) {
            const int t2 = tid + j * 256;
            const int row = t2 >> 2, ch = t2 & 3;
            const int bo = row >> 7, s = row & 127;
            const size_t goff = abase0 + (size_t)bo * bstride + (size_t)s * EE + kb + ch * 8;
            const uint32_t so = row * GP + ch * 16;
            cp_async16(sb + T_A_HI + so, Ah + goff);
            cp_async16(sb + T_A_LO + so, Al + goff);
        }
#pragma unroll
        for (int j = 0; j < 2; ++j) {
            const int t2 = tid + j * 256;
            const int row = t2 >> 2, ch = t2 & 3;
            const size_t goff = wbase + (size_t)row * EE + kb + ch * 8;
            const uint32_t so = row * GP + ch * 16;
            cp_async16(sb + T_B_HI + so, Wh + goff);
            cp_async16(sb + T_B_LO + so, Wl + goff);
        }
    };
    issue(0); cp_commit();
    issue(1); cp_commit();
    issue(2); cp_commit();

    const int wm = wid & 3, wn = wid >> 2;
    const int g = lane >> 3, lr = lane & 7;

    float acc[4][8][4];
#pragma unroll
    for (int mi = 0; mi < 4; ++mi)
#pragma unroll
        for (int nj = 0; nj < 8; ++nj)
#pragma unroll
            for (int r = 0; r < 4; ++r) acc[mi][nj][r] = 0.f;

    for (int it = 0; it < 8; ++it) {
        cp_wait<2>();
        __syncthreads();
        const uint32_t st = sbase + (it % 3) * STAGE;

#pragma unroll
        for (int pass = 0; pass < 3; ++pass) {
            const uint32_t Ab = st + (pass == 2 ? T_A_LO : T_A_HI);
            const uint32_t Bb = st + (pass == 1 ? T_B_LO : T_B_HI);
#pragma unroll
            for (int k16 = 0; k16 < 2; ++k16) {
                uint32_t afr[4][4];
#pragma unroll
                for (int mi = 0; mi < 4; ++mi) {
                    const int row = wm * 64 + mi * 16 + ((g & 1) << 3) + lr;
                    const uint32_t addr = Ab + row * GP + (k16 * 2 + (g >> 1)) * 16;
                    ldsm_x4(afr[mi][0], afr[mi][1], afr[mi][2], afr[mi][3], addr);
                }
                uint32_t bfr[4][4];
#pragma unroll
                for (int ni = 0; ni < 4; ++ni) {
                    const int row = wn * 64 + ni * 16 + ((g >> 1) << 3) + lr;
                    const uint32_t addr = Bb + row * GP + (k16 * 2 + (g & 1)) * 16;
                    ldsm_x4(bfr[ni][0], bfr[ni][1], bfr[ni][2], bfr[ni][3], addr);
                }
#pragma unroll
                for (int mi = 0; mi < 4; ++mi)
#pragma unroll
                    for (int nj = 0; nj < 8; ++nj)
                        mma_bf16(acc[mi][nj], afr[mi],
                                 bfr[nj >> 1][(nj & 1) * 2],
                                 bfr[nj >> 1][(nj & 1) * 2 + 1]);
            }
        }
        __syncthreads();
        if (it + 3 < 8) issue(it + 3);
        cp_commit();
    }

#pragma unroll
    for (int mi = 0; mi < 4; ++mi) {
#pragma unroll
        for (int rr = 0; rr < 2; ++rr) {
            const int m = wm * 64 + mi * 16 + (lane >> 2) + rr * 8;
            const int bo = m >> 7, s = m & 127;
            const size_t yrow = abase0 + (size_t)bo * bstride + (size_t)s * EE + nb * 128;
#pragma unroll
            for (int nj = 0; nj < 8; ++nj) {
                const int col = wn * 64 + nj * 8 + (lane & 3) * 2;
                float v0 = acc[mi][nj][rr * 2 + 0];
                float v1 = acc[mi][nj][rr * 2 + 1];
                if constexpr (EPI == 0) {
                    *(float2*)(Yf + yrow + col) = make_float2(v0, v1);
                } else {
                    const float* bp = bias + (size_t)c * EE + nb * 128 + col;
                    v0 += bp[0];
                    v1 += bp[1];
                    if constexpr (EPI == 1) {
                        v0 = fmaxf(v0, 0.f);
                        v1 = fmaxf(v1, 0.f);
                        __nv_bfloat16 h0, l0, h1, l1;
                        split_bf16(v0, h0, l0);
                        split_bf16(v1, h1, l1);
                        *(__nv_bfloat162*)(Yh + yrow + col) = __halves2bfloat162(h0, h1);
                        *(__nv_bfloat162*)(Yl + yrow + col) = __halves2bfloat162(l0, l1);
                    } else {
                        *(float2*)(Yf + yrow + col) = make_float2(v0, v1);
                    }
                }
            }
        }
    }
}

template <int EPI>
__global__ __launch_bounds__(256) void gemm_mma(
    const __nv_bfloat16* __restrict__ Ah, const __nv_bfloat16* __restrict__ Al,
    const __nv_bfloat16* __restrict__ Wh, const __nv_bfloat16* __restrict__ Wl,
    const float* __restrict__ bias,
    float* __restrict__ Yf,
    __nv_bfloat16* __restrict__ Yh, __nv_bfloat16* __restrict__ Yl)
{
    extern __shared__ __align__(16) char dsm[];
    gemm_body<EPI>(Ah, Al, Wh, Wl, bias, Yf, Yh, Yl,
                   blockIdx.x * 2, blockIdx.y, blockIdx.z, smem_u32(dsm));
}

__global__ __launch_bounds__(256) void gemm_wo_pair(
    const __nv_bfloat16* __restrict__ Ah0, const __nv_bfloat16* __restrict__ Al0,
    const __nv_bfloat16* __restrict__ Wh0, const __nv_bfloat16* __restrict__ Wl0,
    float* __restrict__ Y0,
    const __nv_bfloat16* __restrict__ Ah1, const __nv_bfloat16* __restrict__ Al1,
    const __nv_bfloat16* __restrict__ Wh1, const __nv_bfloat16* __restrict__ Wl1,
    float* __restrict__ Y1)
{
    extern __shared__ __align__(16) char dsm[];
    const int zz = blockIdx.z;
    const int br = zz >= CC;
    const int c = br ? zz - CC : zz;
    gemm_body<0>(br ? Ah1 : Ah0, br ? Al1 : Al0,
                 br ? Wh1 : Wh0, br ? Wl1 : Wl0,
                 nullptr, br ? Y1 : Y0, nullptr, nullptr,
                 blockIdx.x * 2, blockIdx.y, c, smem_u32(dsm));
}

// ---------------------------------------------------------------------------
// Spatial attention (R9 winner): one block per (b,s), 8 heads, 768 thr, 2 CTA/SM.
// ---------------------------------------------------------------------------
constexpr int SA_P = 260;
constexpr int SA_SMEM = (3 * CC * SA_P + HH * CC * 25) * 4;  // 94,080 B

__global__ __launch_bounds__(768, 2) void spatial_attn(
    const float* __restrict__ q, const float* __restrict__ k,
    const float* __restrict__ v, __nv_bfloat16* __restrict__ oh,
    __nv_bfloat16* __restrict__ ol)
{
    extern __shared__ float sa[];
    float* qs = sa;
    float* ks = qs + CC * SA_P;
    float* vs = ks + CC * SA_P;
    float* sc = vs + CC * SA_P;

    const int s = blockIdx.x, b = blockIdx.y;
    const int t = threadIdx.x;
    const size_t gbase = ((size_t)b * CC * SS + s) * EE;
    const size_t cstride = (size_t)SS * EE;

#pragma unroll
    for (int i = 0; i < 2; ++i) {
        const int idx = t + i * 768;
        const int row = idx >> 6, e4 = idx & 63;
        const size_t g = gbase + row * cstride + e4 * 4;
        const int so = row * SA_P + e4 * 4;
        *(float4*)(qs + so) = *(const float4*)(q + g);
        *(float4*)(ks + so) = *(const float4*)(k + g);
        *(float4*)(vs + so) = *(const float4*)(v + g);
    }
    __syncthreads();

    {
        const int h = t / 96;
        const int r = t - h * 96;
        const int cig = r >> 3, dig = r & 7;
        const int ci0 = cig * 2, di0 = dig * 3;
        const float* qb = qs + ci0 * SA_P + h * 32;
        const float* kb = ks + di0 * SA_P + h * 32;
        float a00 = 0.f, a01 = 0.f, a02 = 0.f;
        float a10 = 0.f, a11 = 0.f, a12 = 0.f;
#pragma unroll
        for (int p = 0; p < 32; ++p) {
            const float q0 = qb[p], q1 = qb[SA_P + p];
            const float k0 = kb[p], k1 = kb[SA_P + p], k2 = kb[2 * SA_P + p];
            a00 = fmaf(q0, k0, a00); a01 = fmaf(q0, k1, a01); a02 = fmaf(q0, k2, a02);
            a10 = fmaf(q1, k0, a10); a11 = fmaf(q1, k1, a11); a12 = fmaf(q1, k2, a12);
        }
        float* sr0 = sc + (h * CC + ci0) * 25 + di0;
        float* sr1 = sr0 + 25;
        sr0[0] = a00 * INV_SQRT_P; sr0[1] = a01 * INV_SQRT_P; sr0[2] = a02 * INV_SQRT_P;
        sr1[0] = a10 * INV_SQRT_P; sr1[1] = a11 * INV_SQRT_P; sr1[2] = a12 * INV_SQRT_P;
    }
    __syncthreads();

    if (t < HH * CC) {
        float* row = sc + t * 25;
        float mx = -1e30f;
#pragma unroll
        for (int d = 0; d < CC; ++d) mx = fmaxf(mx, row[d]);
        float sm = 0.f;
#pragma unroll
        for (int d = 0; d < CC; ++d) { float e = __expf(row[d] - mx); row[d] = e; sm += e; }
        const float inv = 1.f / sm;
#pragma unroll
        for (int d = 0; d < CC; ++d) row[d] *= inv;
    }
    __syncthreads();

#pragma unroll
    for (int i = 0; i < 2; ++i) {
        const int item = t + i * 768;
        const int h = item / 192;
        const int rr = item - h * 192;
        const int cc = rr >> 3, p4 = (rr & 7) * 4;
        const float* arow = sc + (h * CC + cc) * 25;
        const float* vb = vs + h * 32 + p4;
        float s0 = 0.f, s1 = 0.f, s2 = 0.f, s3 = 0.f;
#pragma unroll
        for (int d = 0; d < CC; ++d) {
            const float a = arow[d];
            const float4 vv = *(const float4*)(vb + d * SA_P);
            s0 = fmaf(a, vv.x, s0); s1 = fmaf(a, vv.y, s1);
            s2 = fmaf(a, vv.z, s2); s3 = fmaf(a, vv.w, s3);
        }
        const size_t g = gbase + cc * cstride + h * 32 + p4;
        __nv_bfloat16 h0, l0, h1, l1, h2, l2, h3, l3;
        split_bf16(s0, h0, l0); split_bf16(s1, h1, l1);
        split_bf16(s2, h2, l2); split_bf16(s3, h3, l3);
        *(__nv_bfloat162*)(oh + g)     = __halves2bfloat162(h0, h1);
        *(__nv_bfloat162*)(oh + g + 2) = __halves2bfloat162(h2, h3);
        *(__nv_bfloat162*)(ol + g)     = __halves2bfloat162(l0, l1);
        *(__nv_bfloat162*)(ol + g + 2) = __halves2bfloat162(l2, l3);
    }
}

// ---------------------------------------------------------------------------
// Temporal attention v3 — tensor-core flash-style (R12 winner).
// ---------------------------------------------------------------------------
constexpr int TQT_HI = 0;
constexpr int TQT_LO = 128 * GP;             // 10240
constexpr int TKT_HI = 2 * 128 * GP;         // 20480
constexpr int TKT_LO = 3 * 128 * GP;         // 30720
constexpr int TVS_HI = 4 * 128 * GP;         // 40960
constexpr int TVP = 272;                     // V^T pitch (bytes)
constexpr int TVS_LO = TVS_HI + 32 * TVP;    // 49664
constexpr int TEMP_SMEM_BYTES = TVS_LO + 32 * TVP;  // 58368

__global__ __launch_bounds__(256, 2) void temporal_attn(
    const float* __restrict__ q, const float* __restrict__ k,
    const float* __restrict__ v, __nv_bfloat16* __restrict__ oh,
    __nv_bfloat16* __restrict__ ol)
{
    extern __shared__ __align__(16) char tsm[];
    const uint32_t sb = smem_u32(tsm);
    const int c = blockIdx.x, h = blockIdx.y, b = blockIdx.z;
    const int tid = threadIdx.x;
    const int wid = tid >> 5, lane = tid & 31;
    const size_t base = (((size_t)b * CC + c) * SS) * EE + h * PP;

#pragma unroll
    for (int i = 0; i < 4; ++i) {
        const int idx = tid + i * 256;
        const int row = idx >> 3, p4 = (idx & 7) * 4;
        const size_t g = base + (size_t)row * EE + p4;
        {
            float4 vq = *(const float4*)(q + g);
            __nv_bfloat16 hh[4], ll[4];
            split_bf16(vq.x, hh[0], ll[0]); split_bf16(vq.y, hh[1], ll[1]);
            split_bf16(vq.z, hh[2], ll[2]); split_bf16(vq.w, hh[3], ll[3]);
            uint2 hp, lp;
            ((__nv_bfloat162*)&hp)[0] = __halves2bfloat162(hh[0], hh[1]);
            ((__nv_bfloat162*)&hp)[1] = __halves2bfloat162(hh[2], hh[3]);
            ((__nv_bfloat162*)&lp)[0] = __halves2bfloat162(ll[0], ll[1]);
            ((__nv_bfloat162*)&lp)[1] = __halves2bfloat162(ll[2], ll[3]);
            *(uint2*)(tsm + TQT_HI + row * GP + p4 * 2) = hp;
            *(uint2*)(tsm + TQT_LO + row * GP + p4 * 2) = lp;
        }
        {
            float4 vk = *(const float4*)(k + g);
            __nv_bfloat16 hh[4], ll[4];
            split_bf16(vk.x, hh[0], ll[0]); split_bf16(vk.y, hh[1], ll[1]);
            split_bf16(vk.z, hh[2], ll[2]); split_bf16(vk.w, hh[3], ll[3]);
            uint2 hp, lp;
            ((__nv_bfloat162*)&hp)[0] = __halves2bfloat162(hh[0], hh[1]);
            ((__nv_bfloat162*)&hp)[1] = __halves2bfloat162(hh[2], hh[3]);
            ((__nv_bfloat162*)&lp)[0] = __halves2bfloat162(ll[0], ll[1]);
            ((__nv_bfloat162*)&lp)[1] = __halves2bfloat162(ll[2], ll[3]);
            *(uint2*)(tsm + TKT_HI + row * GP + p4 * 2) = hp;
            *(uint2*)(tsm + TKT_LO + row * GP + p4 * 2) = lp;
        }
        {
            float4 vv = *(const float4*)(v + g);
            float vf[4] = {vv.x, vv.y, vv.z, vv.w};
#pragma unroll
            for (int j = 0; j < 4; ++j) {
                __nv_bfloat16 hi, lo;
                split_bf16(vf[j], hi, lo);
                *(__nv_bfloat16*)(tsm + TVS_HI + (p4 + j) * TVP + row * 2) = hi;
                *(__nv_bfloat16*)(tsm + TVS_LO + (p4 + j) * TVP + row * 2) = lo;
            }
        }
    }
    __syncthreads();

    const int g2 = lane >> 3, lr = lane & 7;

    float sacc[16][4];
#pragma unroll
    for (int nj = 0; nj < 16; ++nj)
#pragma unroll
        for (int r = 0; r < 4; ++r) sacc[nj][r] = 0.f;

#pragma unroll
    for (int pass = 0; pass < 3; ++pass) {
        const uint32_t Ab = sb + (pass == 2 ? TQT_LO : TQT_HI);
        const uint32_t Bb = sb + (pass == 1 ? TKT_LO : TKT_HI);
#pragma unroll
        for (int k16 = 0; k16 < 2; ++k16) {
            uint32_t afr[4];
            {
                const int row = wid * 16 + ((g2 & 1) << 3) + lr;
                const uint32_t addr = Ab + row * GP + (k16 * 2 + (g2 >> 1)) * 16;
                ldsm_x4(afr[0], afr[1], afr[2], afr[3], addr);
            }
#pragma unroll
            for (int ni = 0; ni < 8; ++ni) {
                uint32_t bfr[4];
                const int row = ni * 16 + ((g2 >> 1) << 3) + lr;
                const uint32_t addr = Bb + row * GP + (k16 * 2 + (g2 & 1)) * 16;
                ldsm_x4(bfr[0], bfr[1], bfr[2], bfr[3], addr);
                mma_bf16(sacc[ni * 2 + 0], afr, bfr[0], bfr[1]);
                mma_bf16(sacc[ni * 2 + 1], afr, bfr[2], bfr[3]);
            }
        }
    }

#pragma unroll
    for (int nj = 0; nj < 16; ++nj)
#pragma unroll
        for (int r = 0; r < 4; ++r) sacc[nj][r] *= INV_SQRT_P;

    float mx0 = -1e30f, mx1 = -1e30f;
#pragma unroll
    for (int nj = 0; nj < 16; ++nj) {
        mx0 = fmaxf(mx0, fmaxf(sacc[nj][0], sacc[nj][1]));
        mx1 = fmaxf(mx1, fmaxf(sacc[nj][2], sacc[nj][3]));
    }
    mx0 = fmaxf(mx0, __shfl_xor_sync(0xffffffffu, mx0, 1));
    mx0 = fmaxf(mx0, __shfl_xor_sync(0xffffffffu, mx0, 2));
    mx1 = fmaxf(mx1, __shfl_xor_sync(0xffffffffu, mx1, 1));
    mx1 = fmaxf(mx1, __shfl_xor_sync(0xffffffffu, mx1, 2));

    float sum0 = 0.f, sum1 = 0.f;
#pragma unroll
    for (int nj = 0; nj < 16; ++nj) {
        sacc[nj][0] = __expf(sacc[nj][0] - mx0);
        sacc[nj][1] = __expf(sacc[nj][1] - mx0);
        sacc[nj][2] = __expf(sacc[nj][2] - mx1);
        sacc[nj][3] = __expf(sacc[nj][3] - mx1);
        sum0 += sacc[nj][0] + sacc[nj][1];
        sum1 += sacc[nj][2] + sacc[nj][3];
    }
    sum0 += __shfl_xor_sync(0xffffffffu, sum0, 1);
    sum0 += __shfl_xor_sync(0xffffffffu, sum0, 2);
    sum1 += __shfl_xor_sync(0xffffffffu, sum1, 1);
    sum1 += __shfl_xor_sync(0xffffffffu, sum1, 2);
    const float inv0 = 1.f / sum0, inv1 = 1.f / sum1;
#pragma unroll
    for (int nj = 0; nj < 16; ++nj) {
        sacc[nj][0] *= inv0;
        sacc[nj][1] *= inv0;
        sacc[nj][2] *= inv1;
        sacc[nj][3] *= inv1;
    }

    float oacc[4][4];
#pragma unroll
    for (int nj = 0; nj < 4; ++nj)
#pragma unroll
        for (int r = 0; r < 4; ++r) oacc[nj][r] = 0.f;

#pragma unroll
    for (int pass = 0; pass < 3; ++pass) {
        const uint32_t Bb = sb + (pass == 1 ? TVS_LO : TVS_HI);
#pragma unroll
        for (int ki = 0; ki < 8; ++ki) {
            uint32_t a[4];
            if (pass <= 1) {
                a[0] = pack_bf16x2(sacc[2 * ki][0],     sacc[2 * ki][1]);
                a[1] = pack_bf16x2(sacc[2 * ki][2],     sacc[2 * ki][3]);
                a[2] = pack_bf16x2(sacc[2 * ki + 1][0], sacc[2 * ki + 1][1]);
                a[3] = pack_bf16x2(sacc[2 * ki + 1][2], sacc[2 * ki + 1][3]);
            } else {
                a[0] = pack_bf16x2(bf16_lo_res(sacc[2 * ki][0]),     bf16_lo_res(sacc[2 * ki][1]));
                a[1] = pack_bf16x2(bf16_lo_res(sacc[2 * ki][2]),     bf16_lo_res(sacc[2 * ki][3]));
                a[2] = pack_bf16x2(bf16_lo_res(sacc[2 * ki + 1][0]), bf16_lo_res(sacc[2 * ki + 1][1]));
                a[3] = pack_bf16x2(bf16_lo_res(sacc[2 * ki + 1][2]), bf16_lo_res(sacc[2 * ki + 1][3]));
            }
#pragma unroll
            for (int half = 0; half < 2; ++half) {
                uint32_t bfr[4];
                const int row = half * 16 + ((g2 >> 1) << 3) + lr;
                const uint32_t addr = Bb + row * TVP + (ki * 2 + (g2 & 1)) * 16;
                ldsm_x4(bfr[0], bfr[1], bfr[2], bfr[3], addr);
                mma_bf16(oacc[half * 2 + 0], a, bfr[0], bfr[1]);
                mma_bf16(oacc[half * 2 + 1], a, bfr[2], bfr[3]);
            }
        }
    }

    const int r0 = wid * 16 + (lane >> 2);
    const int r1 = r0 + 8;
#pragma unroll
    for (int nj = 0; nj < 4; ++nj) {
        const int col = nj * 8 + (lane & 3) * 2;
        const size_t g0 = base + (size_t)r0 * EE + col;
        const size_t g1 = base + (size_t)r1 * EE + col;
        __nv_bfloat16 h0, l0, h1, l1;
        split_bf16(oacc[nj][0], h0, l0);
        split_bf16(oacc[nj][1], h1, l1);
        *(__nv_bfloat162*)(oh + g0) = __halves2bfloat162(h0, h1);
        *(__nv_bfloat162*)(ol + g0) = __halves2bfloat162(l0, l1);
        split_bf16(oacc[nj][2], h0, l0);
        split_bf16(oacc[nj][3], h1, l1);
        *(__nv_bfloat162*)(oh + g1) = __halves2bfloat162(h0, h1);
        *(__nv_bfloat162*)(ol + g1) = __halves2bfloat162(l0, l1);
    }
}

// ---------------------------------------------------------------------------
// LayerNorm kernels — warp-per-row.
// ---------------------------------------------------------------------------
__device__ __forceinline__ float warp_sum(float v) {
#pragma unroll
    for (int off = 16; off > 0; off >>= 1)
        v += __shfl_xor_sync(0xffffffffu, v, off);
    return v;
}

__global__ __launch_bounds__(256) void dual_ln(
    const float* __restrict__ x, const float* __restrict__ a,
    const float* __restrict__ b2, const float* __restrict__ g,
    const float* __restrict__ beta, float* __restrict__ out,
    __nv_bfloat16* __restrict__ oh, __nv_bfloat16* __restrict__ ol)
{
    const int warp = threadIdx.x >> 5, lane = threadIdx.x & 31;
    const int row = blockIdx.x * 8 + warp;
    const size_t base = (size_t)row * EE;
    const int e0 = lane * 4, e1 = 128 + lane * 4;

    float4 x0 = *(const float4*)(x + base + e0);
    float4 x1 = *(const float4*)(x + base + e1);
    float4 a0 = *(const float4*)(a + base + e0);
    float4 a1 = *(const float4*)(a + base + e1);
    float4 b0 = *(const float4*)(b2 + base + e0);
    float4 b1 = *(const float4*)(b2 + base + e1);

    float v1[8] = {x0.x + a0.x, x0.y + a0.y, x0.z + a0.z, x0.w + a0.w,
                   x1.x + a1.x, x1.y + a1.y, x1.z + a1.z, x1.w + a1.w};
    float v2[8] = {x0.x + b0.x, x0.y + b0.y, x0.z + b0.z, x0.w + b0.w,
                   x1.x + b1.x, x1.y + b1.y, x1.z + b1.z, x1.w + b1.w};

    float s1 = 0.f, q1 = 0.f, s2 = 0.f, q2 = 0.f;
#pragma unroll
    for (int j = 0; j < 8; ++j) {
        s1 += v1[j]; q1 = fmaf(v1[j], v1[j], q1);
        s2 += v2[j]; q2 = fmaf(v2[j], v2[j], q2);
    }
    s1 = warp_sum(s1); q1 = warp_sum(q1);
    s2 = warp_sum(s2); q2 = warp_sum(q2);

    const float invE = 1.f / (float)EE;
    const float m1 = s1 * invE, m2 = s2 * invE;
    const float r1 = rsqrtf(fmaxf(q1 * invE - m1 * m1, 0.f) + LN_EPS);
    const float r2 = rsqrtf(fmaxf(q2 * invE - m2 * m2, 0.f) + LN_EPS);

    float4 g0 = *(const float4*)(g + e0);
    float4 g1 = *(const float4*)(g + e1);
    float4 t0 = *(const float4*)(beta + e0);
    float4 t1 = *(const float4*)(beta + e1);
    float gg[8] = {g0.x, g0.y, g0.z, g0.w, g1.x, g1.y, g1.z, g1.w};
    float bt[8] = {t0.x, t0.y, t0.z, t0.w, t1.x, t1.y, t1.z, t1.w};

    float o[8];
#pragma unroll
    for (int j = 0; j < 8; ++j)
        o[j] = (v1[j] - m1) * r1 * gg[j] + bt[j]
             + (v2[j] - m2) * r2 * gg[j] + bt[j];

    *(float4*)(out + base + e0) = make_float4(o[0], o[1], o[2], o[3]);
    *(float4*)(out + base + e1) = make_float4(o[4], o[5], o[6], o[7]);

    __nv_bfloat16 hh[8], ll[8];
#pragma unroll
    for (int j = 0; j < 8; ++j) split_bf16(o[j], hh[j], ll[j]);
    *(__nv_bfloat162*)(oh + base + e0)     = __halves2bfloat162(hh[0], hh[1]);
    *(__nv_bfloat162*)(oh + base + e0 + 2) = __halves2bfloat162(hh[2], hh[3]);
    *(__nv_bfloat162*)(oh + base + e1)     = __halves2bfloat162(hh[4], hh[5]);
    *(__nv_bfloat162*)(oh + base + e1 + 2) = __halves2bfloat162(hh[6], hh[7]);
    *(__nv_bfloat162*)(ol + base + e0)     = __halves2bfloat162(ll[0], ll[1]);
    *(__nv_bfloat162*)(ol + base + e0 + 2) = __halves2bfloat162(ll[2], ll[3]);
    *(__nv_bfloat162*)(ol + base + e1)     = __halves2bfloat162(ll[4], ll[5]);
    *(__nv_bfloat162*)(ol + base + e1 + 2) = __halves2bfloat162(ll[6], ll[7]);
}

__global__ __launch_bounds__(256) void final_ln(
    const float* __restrict__ a, const float* __restrict__ f,
    const float* __restrict__ g, const float* __restrict__ beta,
    float* __restrict__ out)
{
    const int warp = threadIdx.x >> 5, lane = threadIdx.x & 31;
    const int row = blockIdx.x * 8 + warp;
    const size_t base = (size_t)row * EE;
    const int e0 = lane * 4, e1 = 128 + lane * 4;

    float4 a0 = *(const float4*)(a + base + e0);
    float4 a1 = *(const float4*)(a + base + e1);
    float4 f0 = *(const float4*)(f + base + e0);
    float4 f1 = *(const float4*)(f + base + e1);

    float v[8] = {a0.x + f0.x, a0.y + f0.y, a0.z + f0.z, a0.w + f0.w,
                  a1.x + f1.x, a1.y + f1.y, a1.z + f1.z, a1.w + f1.w};

    float s = 0.f, q = 0.f;
#pragma unroll
    for (int j = 0; j < 8; ++j) { s += v[j]; q = fmaf(v[j], v[j], q); }
    s = warp_sum(s); q = warp_sum(q);

    const float invE = 1.f / (float)EE;
    const float m = s * invE;
    const float r = rsqrtf(fmaxf(q * invE - m * m, 0.f) + LN_EPS);

    float4 g0 = *(const float4*)(g + e0);
    float4 g1 = *(const float4*)(g + e1);
    float4 t0 = *(const float4*)(beta + e0);
    float4 t1 = *(const float4*)(beta + e1);
    float gg[8] = {g0.x, g0.y, g0.z, g0.w, g1.x, g1.y, g1.z, g1.w};
    float bt[8] = {t0.x, t0.y, t0.z, t0.w, t1.x, t1.y, t1.z, t1.w};

    float o[8];
#pragma unroll
    for (int j = 0; j < 8; ++j) o[j] = (v[j] - m) * r * gg[j] + bt[j];
    *(float4*)(out + base + e0) = make_float4(o[0], o[1], o[2], o[3]);
    *(float4*)(out + base + e1) = make_float4(o[4], o[5], o[6], o[7]);
}

// ---------------------------------------------------------------------------
// kernel_launch
// ---------------------------------------------------------------------------
extern "C" void kernel_launch(void* const* d_in, const int* in_sizes, int n_in,
                              void* d_out, int out_size)
{
    const float* x    = (const float*)d_in[0];
    const float* ln_g = (const float*)d_in[9];
    const float* ln_b = (const float*)d_in[10];
    const float* ff_b1 = (const float*)d_in[12];
    const float* ff_b2 = (const float*)d_in[14];
    float* out = (float*)d_out;

    float *qs, *ks, *vs, *qt, *kt, *vt, *spat, *temp, *attn, *ffo;
    __nv_bfloat16 *ah, *al, *hh, *hl, *wh, *wl;
    cudaGetSymbolAddress((void**)&qs,   g_qs);
    cudaGetSymbolAddress((void**)&ks,   g_ks);
    cudaGetSymbolAddress((void**)&vs,   g_vs);
    cudaGetSymbolAddress((void**)&qt,   g_qt);
    cudaGetSymbolAddress((void**)&kt,   g_kt);
    cudaGetSymbolAddress((void**)&vt,   g_vt);
    cudaGetSymbolAddress((void**)&spat, g_spat);
    cudaGetSymbolAddress((void**)&temp, g_temp);
    cudaGetSymbolAddress((void**)&attn, g_attn);
    cudaGetSymbolAddress((void**)&ffo,  g_ffo);
    cudaGetSymbolAddress((void**)&ah, g_ah);
    cudaGetSymbolAddress((void**)&al, g_al);
    cudaGetSymbolAddress((void**)&hh, g_hh);
    cudaGetSymbolAddress((void**)&hl, g_hl);
    cudaGetSymbolAddress((void**)&wh, g_wh);
    cudaGetSymbolAddress((void**)&wl, g_wl);

    cudaFuncSetAttribute(gemm_qkv6,   cudaFuncAttributeMaxDynamicSharedMemorySize, QKV_SMEM);
    cudaFuncSetAttribute(gemm_mma<1>, cudaFuncAttributeMaxDynamicSharedMemorySize, GEMM_SMEM);
    cudaFuncSetAttribute(gemm_mma<2>, cudaFuncAttributeMaxDynamicSharedMemorySize, GEMM_SMEM);
    cudaFuncSetAttribute(gemm_wo_pair, cudaFuncAttributeMaxDynamicSharedMemorySize, GEMM_SMEM);
    cudaFuncSetAttribute(spatial_attn, cudaFuncAttributeMaxDynamicSharedMemorySize, SA_SMEM);
    cudaFuncSetAttribute(temporal_attn, cudaFuncAttributeMaxDynamicSharedMemorySize, TEMP_SMEM_BYTES);

    // ---- weight conversion ----
    WPtrs wp;
    wp.p[0] = (const float*)d_in[1];
    wp.p[1] = (const float*)d_in[2];
    wp.p[2] = (const float*)d_in[3];
    wp.p[3] = (const float*)d_in[4];
    wp.p[4] = (const float*)d_in[5];
    wp.p[5] = (const float*)d_in[6];
    wp.p[6] = (const float*)d_in[7];
    wp.p[7] = (const float*)d_in[8];
    wp.p[8] = (const float*)d_in[11];
    wp.p[9] = (const float*)d_in[13];
    convert_weights_t<<<dim3(64, CC, NW), 256>>>(wp, wh, wl);

    // ---- fused q/k/v projections (x split in-kernel; N=256 blocks) ----
    Out6 o6;
    o6.y[0] = qs; o6.y[1] = ks; o6.y[2] = vs;
    o6.y[3] = qt; o6.y[4] = kt; o6.y[5] = vt;
    gemm_qkv6<<<dim3(BB, 1, CC), 256, QKV_SMEM>>>(x, wh, wl, o6);

    // ---- attentions ----
    spatial_attn<<<dim3(SS, BB), 768, SA_SMEM>>>(qs, ks, vs, ah, al);
    temporal_attn<<<dim3(CC, HH, BB), 256, TEMP_SMEM_BYTES>>>(qt, kt, vt, hh, hl);

    // ---- output projections (merged dual launch, M=256 blocks) ----
    gemm_wo_pair<<<dim3(BB / 2, 2, 2 * CC), 256, GEMM_SMEM>>>(
        ah, al, wh + 3*(size_t)WELEMS, wl + 3*(size_t)WELEMS, spat,
        hh, hl, wh + 7*(size_t)WELEMS, wl + 7*(size_t)WELEMS, temp);

    // ---- residual + dual LN (emits attn fp32 + bf16 pair) ----
    dual_ln<<<NROWS / 8, 256>>>(x, spat, temp, ln_g, ln_b, attn, ah, al);

    // ---- per-joint FF + final LN ----
    gemm_mma<1><<<dim3(BB / 2, 2, CC), 256, GEMM_SMEM>>>(ah, al, wh + 8*(size_t)WELEMS, wl + 8*(size_t)WELEMS, ff_b1, nullptr, hh, hl);
    gemm_mma<2><<<dim3(BB / 2, 2, CC), 256, GEMM_SMEM>>>(hh, hl, wh + 9*(size_t)WELEMS, wl + 9*(size_t)WELEMS, ff_b2, ffo, nullptr, nullptr);
    final_ln<<<NROWS / 8, 256>>>(attn, ffo, ln_g, ln_b, out);
}